// round 5
// baseline (speedup 1.0000x reference)
#include <cuda_runtime.h>

// Problem constants
#define BB     32
#define DD     64
#define HWSZ   4096                 // 64*64
#define NPIX   131072               // BB*HWSZ
#define KK     1024
#define ZSIZE  8388608              // BB*DD*HWSZ
#define ENC_OFF (1 + ZSIZE + 1)     // vq_loss(1), z_q(ZSIZE), perplexity(1), encodings

// Scratch (no device allocation allowed -> __device__ globals)
__device__ int    g_idx[NPIX];
__device__ int    g_counts[KK];
__device__ double g_loss;
__device__ float  g_e2[KK];

// ---------------------------------------------------------------------------
// Kernel 0: per-code ||e||^2 + zero the per-replay scratch
// ---------------------------------------------------------------------------
__global__ void prep_kernel(const float* __restrict__ emb) {
    int k = blockIdx.x * blockDim.x + threadIdx.x;
    if (k < KK) {
        const float4* e4 = (const float4*)(emb + k * 64);
        float s0 = 0.f, s1 = 0.f, s2 = 0.f, s3 = 0.f;
        #pragma unroll
        for (int i = 0; i < 16; i++) {
            float4 v = e4[i];
            s0 += v.x * v.x; s1 += v.y * v.y; s2 += v.z * v.z; s3 += v.w * v.w;
        }
        g_e2[k] = (s0 + s1) + (s2 + s3);
        g_counts[k] = 0;
        if (k == 0) g_loss = 0.0;
    }
}

// ---------------------------------------------------------------------------
// Kernel 1: nearest-code search.
// 256 pixels per block; z row (64 f32) lives in registers; embedding streamed
// through smem in tiles of 128 codes (32 KB). Inner loop is broadcast LDS.128
// + unrolled FFMA -> FMA-pipe bound.
// Distance replicates reference rounding: (x2 + e2[k]) - 2*ip, fp32.
// Strict '<' keeps the first (lowest) index on ties, matching jnp.argmin.
// ---------------------------------------------------------------------------
__global__ __launch_bounds__(256) void argmin_kernel(const float* __restrict__ z,
                                                     const float* __restrict__ emb) {
    __shared__ float4 es4[128 * 16];   // 128 codes x 64 f32
    __shared__ float  e2s[128];

    const int tid = threadIdx.x;
    const int n   = blockIdx.x * 256 + tid;
    const int b   = n >> 12;
    const int hw  = n & 4095;

    // Load z row: z_e is NCHW [B, D, H, W]; for fixed d consecutive tid are
    // consecutive hw -> fully coalesced.
    const float* zp = z + (size_t)b * (DD * HWSZ) + hw;
    float zr[64];
    float xa = 0.f, xb = 0.f, xc = 0.f, xd = 0.f;
    #pragma unroll
    for (int d = 0; d < 64; d += 4) {
        zr[d + 0] = zp[(size_t)(d + 0) * HWSZ];
        zr[d + 1] = zp[(size_t)(d + 1) * HWSZ];
        zr[d + 2] = zp[(size_t)(d + 2) * HWSZ];
        zr[d + 3] = zp[(size_t)(d + 3) * HWSZ];
        xa += zr[d + 0] * zr[d + 0];
        xb += zr[d + 1] * zr[d + 1];
        xc += zr[d + 2] * zr[d + 2];
        xd += zr[d + 3] * zr[d + 3];
    }
    const float x2 = (xa + xb) + (xc + xd);

    float best  = 3.4e38f;
    int   bestk = 0;

    for (int t = 0; t < 8; t++) {
        __syncthreads();
        const float4* src = (const float4*)(emb + (size_t)t * 128 * 64);
        #pragma unroll
        for (int i = tid; i < 128 * 16; i += 256) es4[i] = src[i];
        if (tid < 128) e2s[tid] = g_e2[t * 128 + tid];
        __syncthreads();

        for (int k = 0; k < 128; k++) {
            const float4* ek = es4 + k * 16;   // all lanes same addr: broadcast
            float s0 = 0.f, s1 = 0.f, s2 = 0.f, s3 = 0.f;
            #pragma unroll
            for (int i = 0; i < 16; i++) {
                float4 e4 = ek[i];
                s0 += zr[4 * i + 0] * e4.x;
                s1 += zr[4 * i + 1] * e4.y;
                s2 += zr[4 * i + 2] * e4.z;
                s3 += zr[4 * i + 3] * e4.w;
            }
            float ip   = (s0 + s1) + (s2 + s3);
            float dist = (x2 + e2s[k]) - 2.0f * ip;   // reference-order rounding
            if (dist < best) { best = dist; bestk = t * 128 + k; }
        }
    }

    g_idx[n] = bestk;
    atomicAdd(&g_counts[bestk], 1);
}

// ---------------------------------------------------------------------------
// Kernel 2: z_q (NCHW) gather + sum of squared diffs (for vq_loss)
// ---------------------------------------------------------------------------
__global__ __launch_bounds__(256) void zq_kernel(const float* __restrict__ z,
                                                 const float* __restrict__ emb,
                                                 float* __restrict__ out) {
    const int o  = blockIdx.x * 256 + threadIdx.x;   // < ZSIZE
    const int hw = o & 4095;
    const int bd = o >> 12;          // b*64 + d
    const int d  = bd & 63;
    const int b  = bd >> 6;
    const int n  = (b << 12) | hw;

    const int   k = g_idx[n];
    const float v = emb[k * 64 + d];
    out[1 + o] = v;

    float diff = v - z[o];
    float sq   = diff * diff;
    #pragma unroll
    for (int off = 16; off; off >>= 1) sq += __shfl_down_sync(0xffffffffu, sq, off);

    __shared__ float ws[8];
    const int lane = threadIdx.x & 31, w = threadIdx.x >> 5;
    if (lane == 0) ws[w] = sq;
    __syncthreads();
    if (threadIdx.x == 0) {
        float s = ((ws[0] + ws[1]) + (ws[2] + ws[3])) + ((ws[4] + ws[5]) + (ws[6] + ws[7]));
        atomicAdd(&g_loss, (double)s);
    }
}

// ---------------------------------------------------------------------------
// Kernel 3: one-hot encodings, written in a single pass (zeros + the 1).
// Encodings region starts at float offset ENC_OFF (8-byte aligned only),
// so use float2 stores. One block per row; each thread covers 4 columns.
// ---------------------------------------------------------------------------
__global__ __launch_bounds__(256) void enc_kernel(float* __restrict__ out) {
    const int n   = blockIdx.x;
    const int tid = threadIdx.x;
    const int k   = g_idx[n];

    float v0 = 0.f, v1 = 0.f, v2 = 0.f, v3 = 0.f;
    const int c0 = tid * 4;
    if (k == c0 + 0) v0 = 1.f;
    if (k == c0 + 1) v1 = 1.f;
    if (k == c0 + 2) v2 = 1.f;
    if (k == c0 + 3) v3 = 1.f;

    float2* dst = (float2*)(out + ENC_OFF + (size_t)n * KK + c0);
    dst[0] = make_float2(v0, v1);
    dst[1] = make_float2(v2, v3);
}

// ---------------------------------------------------------------------------
// Kernel 4: vq_loss + perplexity
// ---------------------------------------------------------------------------
__global__ void final_kernel(float* __restrict__ out) {
    __shared__ float ssum[1024];
    const int k = threadIdx.x;
    float p = (float)g_counts[k] * (1.0f / (float)NPIX);
    ssum[k] = p * logf(p + 1e-10f);
    __syncthreads();
    #pragma unroll
    for (int s = 512; s; s >>= 1) {
        if (k < s) ssum[k] += ssum[k + s];
        __syncthreads();
    }
    if (k == 0) {
        out[0]         = (float)(1.25 * g_loss * (1.0 / (double)ZSIZE));
        out[1 + ZSIZE] = expf(-ssum[0]);
    }
}

// ---------------------------------------------------------------------------
extern "C" void kernel_launch(void* const* d_in, const int* in_sizes, int n_in,
                              void* d_out, int out_size) {
    const float* z   = (const float*)d_in[0];   // [32,64,64,64] f32
    const float* emb = (const float*)d_in[1];   // [1024,64] f32
    float* out = (float*)d_out;

    prep_kernel  <<<(KK + 255) / 256, 256>>>(emb);
    argmin_kernel<<<NPIX / 256, 256>>>(z, emb);
    zq_kernel    <<<ZSIZE / 256, 256>>>(z, emb, out);
    enc_kernel   <<<NPIX, 256>>>(out);
    final_kernel <<<1, 1024>>>(out);
}

// round 8
// speedup vs baseline: 1.9869x; 1.9869x over previous
#include <cuda_runtime.h>
#include <cstdint>

// Problem constants
#define BB     32
#define DD     64
#define HWSZ   4096
#define NPIX   131072
#define KK     1024
#define ZSIZE  8388608
#define ENC_OFF (1 + ZSIZE + 1)     // vq_loss(1), z_q, perplexity(1), encodings

#define M_TILE  128                 // pixels per CTA (256 threads, 16 px/warp)
#define PITCH   68                  // z row pitch in words
#define PITCH_B 132                 // B row pitch in words (128 data + 4 pad)

// Shared memory word offsets
#define ZS_W   0                    // z rows:  128 x PITCH           (8704)
#define B0_W   8704                 // B buf0: 128 codes x PITCH_B   (16896)
#define B1_W   25600                // B buf1                        (16896)
#define E2_W   42496                // e2s[1024]
#define X2_W   43520                // x2s[128]
#define BK_W   43648                // bks[128]
#define WS_W   43776                // warp partials[8]
#define SMEM_WORDS 43784
#define SMEM_BYTES (SMEM_WORDS * 4) // 175136 B -> 1 CTA/SM

// Scratch (device globals; no allocation allowed)
__device__ int    g_counts[KK];
__device__ double g_loss;
__device__ float  g_e2[KK];
__device__ __align__(16) float g_embsplit[KK][128]; // [code][tf32-hi d0..63 | tf32-lo d0..63]

// ---------------------------------------------------------------------------
// Helpers
// ---------------------------------------------------------------------------
__device__ __forceinline__ uint32_t smem_u32(const void* p) {
    uint32_t a;
    asm("{ .reg .u64 t; cvta.to.shared.u64 t, %1; cvt.u32.u64 %0, t; }" : "=r"(a) : "l"(p));
    return a;
}
__device__ __forceinline__ uint32_t f2tf32(float x) {
    uint32_t r;
    asm("cvt.rna.tf32.f32 %0, %1;" : "=r"(r) : "f"(x));
    return r;
}
__device__ __forceinline__ void split_tf32(float v, uint32_t& h, uint32_t& l) {
    h = f2tf32(v);
    l = f2tf32(v - __uint_as_float(h));
}
__device__ __forceinline__ void mma_tf32(float c[4], const uint32_t a[4],
                                         uint32_t b0, uint32_t b1) {
    asm volatile("mma.sync.aligned.m16n8k8.row.col.f32.tf32.tf32.f32 "
                 "{%0,%1,%2,%3}, {%4,%5,%6,%7}, {%8,%9}, {%0,%1,%2,%3};"
                 : "+f"(c[0]), "+f"(c[1]), "+f"(c[2]), "+f"(c[3])
                 : "r"(a[0]), "r"(a[1]), "r"(a[2]), "r"(a[3]), "r"(b0), "r"(b1));
}
__device__ __forceinline__ void cp16(uint32_t dst, const void* src) {
    asm volatile("cp.async.cg.shared.global [%0], [%1], 16;" :: "r"(dst), "l"(src));
}
#define CP_COMMIT() asm volatile("cp.async.commit_group;" ::: "memory")
#define CP_WAIT0()  asm volatile("cp.async.wait_group 0;" ::: "memory")

// Stage one 128-code round of the split embedding into a B buffer (cp.async).
// Each code row: 128 words of data at pitch PITCH_B.
__device__ __forceinline__ void stage_B(uint32_t sb, int bufw, int round, int tid) {
    const char* src = (const char*)&g_embsplit[round * 128][0];
    #pragma unroll
    for (int t = 0; t < 16; t++) {
        int idx = tid + t * 256;
        int row = idx >> 5, j = idx & 31;           // 32 x 16B = 512B per row
        uint32_t dst = sb + (uint32_t)(bufw + row * PITCH_B) * 4 + j * 16;
        cp16(dst, src + row * 512 + j * 16);
    }
}

// ---------------------------------------------------------------------------
// Prep: tf32-split embedding, e2 (same formula/order as the passing kernel),
// zero scratch. 4 blocks x 256 threads, one code per thread.
// ---------------------------------------------------------------------------
__global__ void prep_kernel(const float* __restrict__ emb) {
    int k = blockIdx.x * 256 + threadIdx.x;
    const float4* e4 = (const float4*)(emb + k * 64);
    float* dst = g_embsplit[k];
    float s0 = 0.f, s1 = 0.f, s2 = 0.f, s3 = 0.f;
    #pragma unroll
    for (int i = 0; i < 16; i++) {
        float4 v = e4[i];
        s0 += v.x * v.x; s1 += v.y * v.y; s2 += v.z * v.z; s3 += v.w * v.w;
        float vv[4] = {v.x, v.y, v.z, v.w};
        #pragma unroll
        for (int j = 0; j < 4; j++) {
            uint32_t h, l;
            split_tf32(vv[j], h, l);
            dst[4 * i + j]      = __uint_as_float(h);
            dst[64 + 4 * i + j] = __uint_as_float(l);
        }
    }
    g_e2[k] = (s0 + s1) + (s2 + s3);
    g_counts[k] = 0;
    if (k == 0) g_loss = 0.0;
}

// ---------------------------------------------------------------------------
// Main fused kernel: 3xTF32 mma.sync distance GEMM + argmin + z_q + loss +
// counts + single-pass one-hot encodings. 1024 CTAs x 256 threads.
// ---------------------------------------------------------------------------
__global__ __launch_bounds__(256) void vq_main_kernel(const float* __restrict__ z,
                                                      const float* __restrict__ emb,
                                                      float* __restrict__ out) {
    extern __shared__ float sm[];
    const uint32_t sb = smem_u32(sm);
    const int tid = threadIdx.x, lane = tid & 31, wid = tid >> 5;
    const int n0 = blockIdx.x * M_TILE;
    const int b0 = n0 >> 12, hw0 = n0 & 4095;

    float* zs  = sm + ZS_W;
    float* e2s = sm + E2_W;
    float* x2s = sm + X2_W;
    int*   bks = (int*)(sm + BK_W);
    float* ws  = sm + WS_W;

    // ---- stage z rows (coalesced) + e2, prefetch B round 0 ----
    const float* zb = z + (size_t)b0 * (DD * HWSZ) + hw0;
    #pragma unroll
    for (int i = 0; i < 32; i++) {
        int idx = tid + i * 256;
        int d = idx >> 7, p = idx & 127;
        zs[p * PITCH + d] = zb[(size_t)d * HWSZ + p];
    }
    for (int i = tid; i < KK; i += 256) e2s[i] = g_e2[i];
    stage_B(sb, B0_W, 0, tid);
    CP_COMMIT();
    __syncthreads();

    // ---- x2 per pixel (exact round-5 formula/order) ----
    if (tid < 128) {
        const float4* zr4 = (const float4*)(zs + tid * PITCH);
        float s0 = 0.f, s1 = 0.f, s2 = 0.f, s3 = 0.f;
        #pragma unroll
        for (int i = 0; i < 16; i++) {
            float4 v = zr4[i];
            s0 += v.x * v.x; s1 += v.y * v.y; s2 += v.z * v.z; s3 += v.w * v.w;
        }
        x2s[tid] = (s0 + s1) + (s2 + s3);
    }

    // ---- build persistent A fragments (16 pixels per warp, 8 ksteps, hi/lo) ----
    uint32_t AH[8][4], AL[8][4];
    const int r0 = wid * 16 + (lane >> 2), r1 = r0 + 8, kq = lane & 3;
    #pragma unroll
    for (int ks = 0; ks < 8; ks++) {
        float v0 = zs[r0 * PITCH + ks * 8 + kq];
        float v1 = zs[r1 * PITCH + ks * 8 + kq];
        float v2 = zs[r0 * PITCH + ks * 8 + kq + 4];
        float v3 = zs[r1 * PITCH + ks * 8 + kq + 4];
        split_tf32(v0, AH[ks][0], AL[ks][0]);
        split_tf32(v1, AH[ks][1], AL[ks][1]);
        split_tf32(v2, AH[ks][2], AL[ks][2]);
        split_tf32(v3, AH[ks][3], AL[ks][3]);
    }

    CP_WAIT0();
    __syncthreads();               // B0 + x2s ready

    const float x2a = x2s[r0], x2b = x2s[r1];
    float best0 = 3.4e38f, best1 = 3.4e38f;
    int   bk0 = 0, bk1 = 0;

    // ---- 8 rounds x 128 codes, double-buffered ----
    for (int rd = 0; rd < 8; rd++) {
        if (rd < 7) { stage_B(sb, ((rd + 1) & 1) ? B1_W : B0_W, rd + 1, tid); CP_COMMIT(); }
        const float* Bs = sm + ((rd & 1) ? B1_W : B0_W);
        const int kb = rd * 128;

        for (int pair = 0; pair < 8; pair++) {     // 2 ntiles (16 codes) per iter
            float c[2][4] = {{0.f,0.f,0.f,0.f},{0.f,0.f,0.f,0.f}};
            const int code0 = (pair * 2 + 0) * 8 + (lane >> 2);
            const int code1 = (pair * 2 + 1) * 8 + (lane >> 2);
            #pragma unroll
            for (int ks = 0; ks < 8; ks++) {
                const float* p0 = Bs + code0 * PITCH_B + ks * 8 + kq;
                const float* p1 = Bs + code1 * PITCH_B + ks * 8 + kq;
                uint32_t bh00 = __float_as_uint(p0[0]);
                uint32_t bh01 = __float_as_uint(p0[4]);
                uint32_t bl00 = __float_as_uint(p0[64]);
                uint32_t bl01 = __float_as_uint(p0[68]);
                uint32_t bh10 = __float_as_uint(p1[0]);
                uint32_t bh11 = __float_as_uint(p1[4]);
                uint32_t bl10 = __float_as_uint(p1[64]);
                uint32_t bl11 = __float_as_uint(p1[68]);
                mma_tf32(c[0], AH[ks], bh00, bh01);
                mma_tf32(c[1], AH[ks], bh10, bh11);
                mma_tf32(c[0], AL[ks], bh00, bh01);
                mma_tf32(c[1], AL[ks], bh10, bh11);
                mma_tf32(c[0], AH[ks], bl00, bl01);
                mma_tf32(c[1], AH[ks], bl10, bl11);
            }
            // Epilogue: dist = (x2 + e2) - 2*ip, fp32 (reference rounding order).
            #pragma unroll
            for (int t = 0; t < 2; t++) {
                const int cbase = kb + (pair * 2 + t) * 8 + 2 * kq;
                float e0 = e2s[cbase], e1 = e2s[cbase + 1];
                float d0 = (x2a + e0) - 2.0f * c[t][0];
                float d1 = (x2a + e1) - 2.0f * c[t][1];
                float d2 = (x2b + e0) - 2.0f * c[t][2];
                float d3 = (x2b + e1) - 2.0f * c[t][3];
                if (d0 < best0) { best0 = d0; bk0 = cbase; }
                if (d1 < best0) { best0 = d1; bk0 = cbase + 1; }
                if (d2 < best1) { best1 = d2; bk1 = cbase; }
                if (d3 < best1) { best1 = d3; bk1 = cbase + 1; }
            }
        }
        if (rd < 7) { CP_WAIT0(); __syncthreads(); }
    }

    // ---- quad reduce (ties -> lowest index, matching jnp.argmin) ----
    #pragma unroll
    for (int off = 1; off <= 2; off <<= 1) {
        float od0 = __shfl_xor_sync(0xffffffffu, best0, off);
        int   ok0 = __shfl_xor_sync(0xffffffffu, bk0, off);
        if (od0 < best0 || (od0 == best0 && ok0 < bk0)) { best0 = od0; bk0 = ok0; }
        float od1 = __shfl_xor_sync(0xffffffffu, best1, off);
        int   ok1 = __shfl_xor_sync(0xffffffffu, bk1, off);
        if (od1 < best1 || (od1 == best1 && ok1 < bk1)) { best1 = od1; bk1 = ok1; }
    }
    if ((lane & 3) == 0) { bks[r0] = bk0; bks[r1] = bk1; }
    __syncthreads();

    // ---- outputs (validated round-5 logic) ----
    if (tid < 128) {
        const int n  = n0 + tid;
        const int k  = bks[tid];
        atomicAdd(&g_counts[k], 1);

        const float4* erow = (const float4*)(emb + k * 64);
        const float4* zr4  = (const float4*)(zs + tid * PITCH);
        float* o_zq = out + 1 + (size_t)b0 * (DD * HWSZ) + (n & 4095);
        float sq = 0.f;
        #pragma unroll
        for (int i = 0; i < 16; i++) {
            float4 v = erow[i];
            float4 zv = zr4[i];
            o_zq[(size_t)(4 * i + 0) * HWSZ] = v.x;
            o_zq[(size_t)(4 * i + 1) * HWSZ] = v.y;
            o_zq[(size_t)(4 * i + 2) * HWSZ] = v.z;
            o_zq[(size_t)(4 * i + 3) * HWSZ] = v.w;
            float d0 = v.x - zv.x, d1 = v.y - zv.y, d2 = v.z - zv.z, d3 = v.w - zv.w;
            sq += d0 * d0 + d1 * d1 + d2 * d2 + d3 * d3;
        }
        #pragma unroll
        for (int off = 16; off; off >>= 1) sq += __shfl_down_sync(0xffffffffu, sq, off);
        if (lane == 0) ws[wid] = sq;
    }
    __syncthreads();
    if (tid == 0) atomicAdd(&g_loss, (double)((ws[0] + ws[1]) + (ws[2] + ws[3])));

    // One-hot encodings: 512KB per CTA, STG.128 aligned body.
    {
        const size_t base = (size_t)ENC_OFF + (size_t)n0 * KK;
        if (tid == 0) {
            int kk0 = bks[0];
            out[base + 0] = (kk0 == 0) ? 1.f : 0.f;
            out[base + 1] = (kk0 == 1) ? 1.f : 0.f;
        }
        if (tid == 1) {
            int kl = bks[127];
            out[base + (size_t)127 * 1024 + 1022] = (kl == 1022) ? 1.f : 0.f;
            out[base + (size_t)127 * 1024 + 1023] = (kl == 1023) ? 1.f : 0.f;
        }
        float4* enc4 = (float4*)(out + base + 2);   // 16B aligned
        for (int q = tid; q < 32767; q += 256) {
            int p = 2 + 4 * q;
            int row = p >> 10, col = p & 1023;
            int k0 = bks[row];
            float4 v;
            if (col <= 1020) {
                v.x = (col     == k0) ? 1.f : 0.f;
                v.y = (col + 1 == k0) ? 1.f : 0.f;
                v.z = (col + 2 == k0) ? 1.f : 0.f;
                v.w = (col + 3 == k0) ? 1.f : 0.f;
            } else {  // col == 1022 spans rows row / row+1
                int k1 = bks[row + 1];
                v.x = (1022 == k0) ? 1.f : 0.f;
                v.y = (1023 == k0) ? 1.f : 0.f;
                v.z = (0 == k1) ? 1.f : 0.f;
                v.w = (1 == k1) ? 1.f : 0.f;
            }
            enc4[q] = v;
        }
    }
}

// ---------------------------------------------------------------------------
// Final: vq_loss + perplexity
// ---------------------------------------------------------------------------
__global__ void final_kernel(float* __restrict__ out) {
    __shared__ float ssum[1024];
    const int k = threadIdx.x;
    float p = (float)g_counts[k] * (1.0f / (float)NPIX);
    ssum[k] = p * logf(p + 1e-10f);
    __syncthreads();
    #pragma unroll
    for (int s = 512; s; s >>= 1) {
        if (k < s) ssum[k] += ssum[k + s];
        __syncthreads();
    }
    if (k == 0) {
        out[0]         = (float)(1.25 * g_loss * (1.0 / (double)ZSIZE));
        out[1 + ZSIZE] = expf(-ssum[0]);
    }
}

// ---------------------------------------------------------------------------
extern "C" void kernel_launch(void* const* d_in, const int* in_sizes, int n_in,
                              void* d_out, int out_size) {
    const float* z   = (const float*)d_in[0];   // [32,64,64,64] f32 NCHW
    const float* emb = (const float*)d_in[1];   // [1024,64] f32
    float* out = (float*)d_out;

    cudaFuncSetAttribute(vq_main_kernel, cudaFuncAttributeMaxDynamicSharedMemorySize,
                         SMEM_BYTES);

    prep_kernel   <<<KK / 256, 256>>>(emb);
    vq_main_kernel<<<NPIX / M_TILE, 256, SMEM_BYTES>>>(z, emb, out);
    final_kernel  <<<1, 1024>>>(out);
}

// round 9
// speedup vs baseline: 3.6947x; 1.8596x over previous
#include <cuda_runtime.h>
#include <cuda_fp16.h>
#include <cstdint>

// Problem constants
#define BB     32
#define DD     64
#define HWSZ   4096
#define NPIX   131072
#define KK     1024
#define ZSIZE  8388608
#define ENC_OFF (1 + ZSIZE + 1)     // vq_loss(1), z_q, perplexity(1), encodings

#define M_TILE  128                 // pixels per CTA (256 threads, 16 px/warp)
#define PITCH   68                  // z row pitch in words
#define PITCH_B 68                  // B row pitch in words (64 half2 words + 4 pad)

// Shared memory word offsets
#define ZS_W   0                    // z rows: 128 x PITCH            (8704)
#define B0_W   8704                 // B buf0: 128 codes x PITCH_B    (8704)
#define B1_W   17408                // B buf1                         (8704)
#define E2_W   26112                // e2s[1024]
#define X2_W   27136                // x2s[128]
#define BK_W   27264                // bks[128]
#define WS_W   27392                // warp partials[8]
#define SMEM_WORDS 27400
#define SMEM_BYTES (SMEM_WORDS * 4) // 109600 B -> 2 CTAs/SM possible

// Scratch (device globals; no allocation allowed)
__device__ int    g_counts[KK];
__device__ double g_loss;
__device__ float  g_e2[KK];
// Packed fp16-split embedding, scaled by 1024:
// [code][ hi half2 words j=0..31 (k=2j,2j+1) | lo half2 words 32..63 ]
__device__ __align__(16) uint32_t g_embpack[KK][64];

// ---------------------------------------------------------------------------
// Helpers
// ---------------------------------------------------------------------------
__device__ __forceinline__ uint32_t smem_u32(const void* p) {
    uint32_t a;
    asm("{ .reg .u64 t; cvta.to.shared.u64 t, %1; cvt.u32.u64 %0, t; }" : "=r"(a) : "l"(p));
    return a;
}
__device__ __forceinline__ uint32_t pack_h2(float a, float b) {
    __half2 h = __halves2half2(__float2half_rn(a), __float2half_rn(b));
    return *(uint32_t*)&h;
}
// fp16 hi/lo split of two floats -> packed half2 words
__device__ __forceinline__ void split_f16x2(float a, float b, uint32_t& h, uint32_t& l) {
    __half ha = __float2half_rn(a), hb = __float2half_rn(b);
    float ra = a - __half2float(ha), rb = b - __half2float(hb);
    __half2 hh = __halves2half2(ha, hb);
    h = *(uint32_t*)&hh;
    l = pack_h2(ra, rb);
}
__device__ __forceinline__ void mma_f16(float c[4], const uint32_t a[4],
                                        uint32_t b0, uint32_t b1) {
    asm volatile("mma.sync.aligned.m16n8k16.row.col.f32.f16.f16.f32 "
                 "{%0,%1,%2,%3}, {%4,%5,%6,%7}, {%8,%9}, {%0,%1,%2,%3};"
                 : "+f"(c[0]), "+f"(c[1]), "+f"(c[2]), "+f"(c[3])
                 : "r"(a[0]), "r"(a[1]), "r"(a[2]), "r"(a[3]), "r"(b0), "r"(b1));
}
__device__ __forceinline__ void cp16(uint32_t dst, const void* src) {
    asm volatile("cp.async.cg.shared.global [%0], [%1], 16;" :: "r"(dst), "l"(src));
}
#define CP_COMMIT() asm volatile("cp.async.commit_group;" ::: "memory")
#define CP_WAIT0()  asm volatile("cp.async.wait_group 0;" ::: "memory")

// Stage one 128-code round: 128 rows x 256B at pitch 272B (= 17 x 16B, aligned).
__device__ __forceinline__ void stage_B(uint32_t sb, int bufw, int round, int tid) {
    const char* src = (const char*)&g_embpack[round * 128][0];
    #pragma unroll
    for (int t = 0; t < 8; t++) {
        int idx = tid + t * 256;
        int row = idx >> 4, j = idx & 15;           // 16 x 16B = 256B per row
        uint32_t dst = sb + (uint32_t)(bufw + row * PITCH_B) * 4 + j * 16;
        cp16(dst, src + row * 256 + j * 16);
    }
}

// ---------------------------------------------------------------------------
// Prep: one code per warp. e2 (warp-reduced), fp16-split of 1024*e packed
// into g_embpack, zero scratch. Grid 128 x 256.
// ---------------------------------------------------------------------------
__global__ void prep_kernel(const float* __restrict__ emb) {
    const int code = blockIdx.x * 8 + (threadIdx.x >> 5);
    const int lane = threadIdx.x & 31;
    float2 v = ((const float2*)(emb + code * 64))[lane];

    float sq = v.x * v.x + v.y * v.y;
    #pragma unroll
    for (int off = 16; off; off >>= 1) sq += __shfl_xor_sync(0xffffffffu, sq, off);
    if (lane == 0) g_e2[code] = sq;

    uint32_t h, l;
    split_f16x2(v.x * 1024.0f, v.y * 1024.0f, h, l);
    g_embpack[code][lane]      = h;
    g_embpack[code][32 + lane] = l;

    int gid = blockIdx.x * 256 + threadIdx.x;
    if (gid < KK) g_counts[gid] = 0;
    if (gid == 0) g_loss = 0.0;
}

// ---------------------------------------------------------------------------
// Main fused kernel: 3-term fp16-split mma.sync distance GEMM + argmin +
// z_q + loss + counts + single-pass one-hot encodings. 1024 CTAs x 256 thr.
// ---------------------------------------------------------------------------
__global__ __launch_bounds__(256, 2) void vq_main_kernel(const float* __restrict__ z,
                                                         const float* __restrict__ emb,
                                                         float* __restrict__ out) {
    extern __shared__ float sm[];
    const uint32_t sb = smem_u32(sm);
    const int tid = threadIdx.x, lane = tid & 31, wid = tid >> 5;
    const int n0 = blockIdx.x * M_TILE;
    const int b0 = n0 >> 12, hw0 = n0 & 4095;

    float* zs  = sm + ZS_W;
    float* e2s = sm + E2_W;
    float* x2s = sm + X2_W;
    int*   bks = (int*)(sm + BK_W);
    float* ws  = sm + WS_W;

    // ---- stage z rows (coalesced) + e2, prefetch B round 0 ----
    const float* zb = z + (size_t)b0 * (DD * HWSZ) + hw0;
    #pragma unroll
    for (int i = 0; i < 32; i++) {
        int idx = tid + i * 256;
        int d = idx >> 7, p = idx & 127;
        zs[p * PITCH + d] = zb[(size_t)d * HWSZ + p];
    }
    for (int i = tid; i < KK; i += 256) e2s[i] = g_e2[i];
    stage_B(sb, B0_W, 0, tid);
    CP_COMMIT();
    __syncthreads();

    // ---- x2 per pixel (exact round-5 formula/order) ----
    if (tid < 128) {
        const float4* zr4 = (const float4*)(zs + tid * PITCH);
        float s0 = 0.f, s1 = 0.f, s2 = 0.f, s3 = 0.f;
        #pragma unroll
        for (int i = 0; i < 16; i++) {
            float4 v = zr4[i];
            s0 += v.x * v.x; s1 += v.y * v.y; s2 += v.z * v.z; s3 += v.w * v.w;
        }
        x2s[tid] = (s0 + s1) + (s2 + s3);
    }

    // ---- persistent A fragments: m16n8k16, 4 ksteps, hi/lo splits ----
    // a0: row r0, k=16ks+2kq,+1 | a1: row r1 same | a2: r0, +8 | a3: r1, +8
    uint32_t AH[4][4], AL[4][4];
    const int r0 = wid * 16 + (lane >> 2), r1 = r0 + 8, kq = lane & 3;
    #pragma unroll
    for (int ks = 0; ks < 4; ks++) {
        const int kbse = 16 * ks + 2 * kq;
        split_f16x2(zs[r0 * PITCH + kbse],     zs[r0 * PITCH + kbse + 1], AH[ks][0], AL[ks][0]);
        split_f16x2(zs[r1 * PITCH + kbse],     zs[r1 * PITCH + kbse + 1], AH[ks][1], AL[ks][1]);
        split_f16x2(zs[r0 * PITCH + kbse + 8], zs[r0 * PITCH + kbse + 9], AH[ks][2], AL[ks][2]);
        split_f16x2(zs[r1 * PITCH + kbse + 8], zs[r1 * PITCH + kbse + 9], AH[ks][3], AL[ks][3]);
    }

    CP_WAIT0();
    __syncthreads();               // B0 + x2s ready

    const float x2a = x2s[r0], x2b = x2s[r1];
    float best0 = 3.4e38f, best1 = 3.4e38f;
    int   bk0 = 0, bk1 = 0;

    // ---- 8 rounds x 128 codes, double-buffered ----
    for (int rd = 0; rd < 8; rd++) {
        if (rd < 7) { stage_B(sb, ((rd + 1) & 1) ? B1_W : B0_W, rd + 1, tid); CP_COMMIT(); }
        const float* Bs = sm + ((rd & 1) ? B1_W : B0_W);
        const int kb = rd * 128;

        for (int pair = 0; pair < 8; pair++) {     // 2 ntiles (16 codes) per iter
            float c[2][4] = {{0.f,0.f,0.f,0.f},{0.f,0.f,0.f,0.f}};
            const int code0 = (pair * 2 + 0) * 8 + (lane >> 2);
            const int code1 = (pair * 2 + 1) * 8 + (lane >> 2);
            const uint32_t* q0 = (const uint32_t*)Bs + code0 * PITCH_B;
            const uint32_t* q1 = (const uint32_t*)Bs + code1 * PITCH_B;
            #pragma unroll
            for (int ks = 0; ks < 4; ks++) {
                const int j = 8 * ks + kq;
                uint32_t bh00 = q0[j],      bh01 = q0[j + 4];
                uint32_t bl00 = q0[j + 32], bl01 = q0[j + 36];
                uint32_t bh10 = q1[j],      bh11 = q1[j + 4];
                uint32_t bl10 = q1[j + 32], bl11 = q1[j + 36];
                mma_f16(c[0], AH[ks], bh00, bh01);
                mma_f16(c[1], AH[ks], bh10, bh11);
                mma_f16(c[0], AL[ks], bh00, bh01);
                mma_f16(c[1], AL[ks], bh10, bh11);
                mma_f16(c[0], AH[ks], bl00, bl01);
                mma_f16(c[1], AH[ks], bl10, bl11);
            }
            // dist = (x2 + e2) - 2*ip, fp32; ip = c * 2^-10 (exact unscale)
            #pragma unroll
            for (int t = 0; t < 2; t++) {
                const int cbase = kb + (pair * 2 + t) * 8 + 2 * kq;
                float e0 = e2s[cbase], e1 = e2s[cbase + 1];
                float d0 = (x2a + e0) - 2.0f * (c[t][0] * (1.0f / 1024.0f));
                float d1 = (x2a + e1) - 2.0f * (c[t][1] * (1.0f / 1024.0f));
                float d2 = (x2b + e0) - 2.0f * (c[t][2] * (1.0f / 1024.0f));
                float d3 = (x2b + e1) - 2.0f * (c[t][3] * (1.0f / 1024.0f));
                if (d0 < best0) { best0 = d0; bk0 = cbase; }
                if (d1 < best0) { best0 = d1; bk0 = cbase + 1; }
                if (d2 < best1) { best1 = d2; bk1 = cbase; }
                if (d3 < best1) { best1 = d3; bk1 = cbase + 1; }
            }
        }
        if (rd < 7) { CP_WAIT0(); __syncthreads(); }
    }

    // ---- quad reduce (ties -> lowest index, matching jnp.argmin) ----
    #pragma unroll
    for (int off = 1; off <= 2; off <<= 1) {
        float od0 = __shfl_xor_sync(0xffffffffu, best0, off);
        int   ok0 = __shfl_xor_sync(0xffffffffu, bk0, off);
        if (od0 < best0 || (od0 == best0 && ok0 < bk0)) { best0 = od0; bk0 = ok0; }
        float od1 = __shfl_xor_sync(0xffffffffu, best1, off);
        int   ok1 = __shfl_xor_sync(0xffffffffu, bk1, off);
        if (od1 < best1 || (od1 == best1 && ok1 < bk1)) { best1 = od1; bk1 = ok1; }
    }
    if ((lane & 3) == 0) { bks[r0] = bk0; bks[r1] = bk1; }
    __syncthreads();

    // ---- outputs (validated round-5/8 logic) ----
    if (tid < 128) {
        const int n  = n0 + tid;
        const int k  = bks[tid];
        atomicAdd(&g_counts[k], 1);

        const float4* erow = (const float4*)(emb + k * 64);
        const float4* zr4  = (const float4*)(zs + tid * PITCH);
        float* o_zq = out + 1 + (size_t)b0 * (DD * HWSZ) + (n & 4095);
        float sq = 0.f;
        #pragma unroll
        for (int i = 0; i < 16; i++) {
            float4 v = erow[i];
            float4 zv = zr4[i];
            o_zq[(size_t)(4 * i + 0) * HWSZ] = v.x;
            o_zq[(size_t)(4 * i + 1) * HWSZ] = v.y;
            o_zq[(size_t)(4 * i + 2) * HWSZ] = v.z;
            o_zq[(size_t)(4 * i + 3) * HWSZ] = v.w;
            float d0 = v.x - zv.x, d1 = v.y - zv.y, d2 = v.z - zv.z, d3 = v.w - zv.w;
            sq += d0 * d0 + d1 * d1 + d2 * d2 + d3 * d3;
        }
        #pragma unroll
        for (int off = 16; off; off >>= 1) sq += __shfl_down_sync(0xffffffffu, sq, off);
        if (lane == 0) ws[wid] = sq;
    }
    __syncthreads();
    if (tid == 0) atomicAdd(&g_loss, (double)((ws[0] + ws[1]) + (ws[2] + ws[3])));

    // One-hot encodings: 512KB per CTA, STG.128 aligned body.
    {
        const size_t base = (size_t)ENC_OFF + (size_t)n0 * KK;
        if (tid == 0) {
            int kk0 = bks[0];
            out[base + 0] = (kk0 == 0) ? 1.f : 0.f;
            out[base + 1] = (kk0 == 1) ? 1.f : 0.f;
        }
        if (tid == 1) {
            int kl = bks[127];
            out[base + (size_t)127 * 1024 + 1022] = (kl == 1022) ? 1.f : 0.f;
            out[base + (size_t)127 * 1024 + 1023] = (kl == 1023) ? 1.f : 0.f;
        }
        float4* enc4 = (float4*)(out + base + 2);   // 16B aligned
        for (int q = tid; q < 32767; q += 256) {
            int p = 2 + 4 * q;
            int row = p >> 10, col = p & 1023;
            int k0 = bks[row];
            float4 v;
            if (col <= 1020) {
                v.x = (col     == k0) ? 1.f : 0.f;
                v.y = (col + 1 == k0) ? 1.f : 0.f;
                v.z = (col + 2 == k0) ? 1.f : 0.f;
                v.w = (col + 3 == k0) ? 1.f : 0.f;
            } else {  // col == 1022 spans rows row / row+1
                int k1 = bks[row + 1];
                v.x = (1022 == k0) ? 1.f : 0.f;
                v.y = (1023 == k0) ? 1.f : 0.f;
                v.z = (0 == k1) ? 1.f : 0.f;
                v.w = (1 == k1) ? 1.f : 0.f;
            }
            enc4[q] = v;
        }
    }
}

// ---------------------------------------------------------------------------
// Final: vq_loss + perplexity
// ---------------------------------------------------------------------------
__global__ void final_kernel(float* __restrict__ out) {
    __shared__ float ssum[1024];
    const int k = threadIdx.x;
    float p = (float)g_counts[k] * (1.0f / (float)NPIX);
    ssum[k] = p * logf(p + 1e-10f);
    __syncthreads();
    #pragma unroll
    for (int s = 512; s; s >>= 1) {
        if (k < s) ssum[k] += ssum[k + s];
        __syncthreads();
    }
    if (k == 0) {
        out[0]         = (float)(1.25 * g_loss * (1.0 / (double)ZSIZE));
        out[1 + ZSIZE] = expf(-ssum[0]);
    }
}

// ---------------------------------------------------------------------------
extern "C" void kernel_launch(void* const* d_in, const int* in_sizes, int n_in,
                              void* d_out, int out_size) {
    const float* z   = (const float*)d_in[0];   // [32,64,64,64] f32 NCHW
    const float* emb = (const float*)d_in[1];   // [1024,64] f32
    float* out = (float*)d_out;

    cudaFuncSetAttribute(vq_main_kernel, cudaFuncAttributeMaxDynamicSharedMemorySize,
                         SMEM_BYTES);

    prep_kernel   <<<KK / 8, 256>>>(emb);
    vq_main_kernel<<<NPIX / M_TILE, 256, SMEM_BYTES>>>(z, emb, out);
    final_kernel  <<<1, 1024>>>(out);
}